// round 7
// baseline (speedup 1.0000x reference)
#include <cuda_runtime.h>
#include <cuda_bf16.h>
#include <cooperative_groups.h>
namespace cg = cooperative_groups;

// One-kernel collision pipeline as a SINGLE 8-CTA cluster (8 x 1024 threads,
// 1 body/thread). HW cluster barriers replace software global barriers; the
// cross-block prefix is 8 DSMEM reads of per-CTA packed totals. Narrow phase
// fused into the ring query; exact reference compaction semantics:
// row-major ascending (i,j) candidates, cutoffs limit_broad=4N / limit_narrow=N.
//
// N=8192, BOX=112, radii in [0.5,1.0) -> rsum < 2.0 -> grid cell 2.0 (56x56);
// all AABB-overlapping pairs lie within the +-1 cell ring.

#define MAXN  8192
#define MAXB  (4 * MAXN)
#define GDIM  56
#define NCELL (GDIM * GDIM)
#define CAPC  20            // bodies/cell cap (avg 2.6; Poisson tail safe)
#define CAPR  32            // candidates/row cap (avg ~4; tail safe)
#define NCLUS 8
#define NTPB  1024
#define NTH   (NCLUS * NTPB)

typedef unsigned long long ull;

__device__ int    g_cellcnt[NCELL];            // zero-init; re-zeroed in-kernel
__device__ float4 g_cellslot[NCELL * CAPC];    // x, y, r, body-index bits

__global__ __launch_bounds__(NTPB, 1) __cluster_dims__(NCLUS, 1, 1)
void collide_kernel(const float2* __restrict__ c,
                    const float*  __restrict__ r,
                    const int*    __restrict__ d_lb,
                    const int*    __restrict__ d_ln,
                    float*        __restrict__ out, int n) {
    cg::cluster_group cluster = cg::this_cluster();
    __shared__ ull s_warp[32];
    __shared__ ull s_tot;                      // this CTA's packed total
    __shared__ ull s_peer[NCLUS];
    const int t    = threadIdx.x;
    const int lane = t & 31;
    const int wid  = t >> 5;
    const int crank = (int)cluster.block_rank();
    const int gid   = crank * NTPB + t;

    // ---- P1: load body, copy centers to out, insert into grid ----
    float2 ci = make_float2(0.f, 0.f);
    float  ri = 0.f;
    int cx = 0, cy = 0;
    if (gid < n) {
        ci = c[gid];
        ri = r[gid];
        ((float2*)out)[gid] = ci;
        cx = min(GDIM - 1, max(0, (int)(ci.x * 0.5f)));
        cy = min(GDIM - 1, max(0, (int)(ci.y * 0.5f)));
        int cell = cy * GDIM + cx;
        int slot = atomicAdd(&g_cellcnt[cell], 1);
        if (slot < CAPC)
            g_cellslot[cell * CAPC + slot] =
                make_float4(ci.x, ci.y, ri, __int_as_float(gid));
    }
    cluster.sync();    // CS1: grid built (HW barrier, whole problem = 1 cluster)

    // ---- P2: prefetch 9 ring-cell counts (MLP), then query + fused narrow ----
    int keys[CAPR];                          // (j<<1) | hit  (LMEM, L1-resident)
    float hdx[CAPR], hdy[CAPR], hrs[CAPR];   // per-hit data (no reloads later)
    int cnt = 0, hitcnt = 0;
    if (gid < n) {
        int cell9[9], cc9[9];
        #pragma unroll
        for (int s = 0; s < 9; s++) {
            int yy = cy + s / 3 - 1;
            int xx = cx + s % 3 - 1;
            bool v = (yy >= 0) & (yy < GDIM) & (xx >= 0) & (xx < GDIM);
            int cell = v ? yy * GDIM + xx : 0;
            cell9[s] = cell;
            cc9[s]   = v ? g_cellcnt[cell] : 0;   // 9 independent LDGs
        }
        #pragma unroll
        for (int s = 0; s < 9; s++) {
            int cc = min(cc9[s], CAPC);
            const float4* base = &g_cellslot[cell9[s] * CAPC];
            for (int q = 0; q < cc; q++) {
                float4 b = base[q];
                int j = __float_as_int(b.w);
                if (j <= gid) continue;
                float rs = ri + b.z;
                float dx = b.x - ci.x;
                float dy = b.y - ci.y;
                if (fabsf(dx) <= rs && fabsf(dy) <= rs) {
                    if (cnt < CAPR) {
                        // depth>0  <=>  d2 + eps < rs^2
                        float d2 = dx * dx + dy * dy + 1e-12f;
                        int hit = (d2 < rs * rs) ? 1 : 0;
                        keys[cnt] = (j << 1) | hit;
                        if (hit) {
                            hdx[cnt] = dx; hdy[cnt] = dy; hrs[cnt] = rs;
                            hitcnt++;
                        }
                    }
                    cnt++;
                }
            }
        }
        if (cnt > CAPR) cnt = CAPR;
    }

    // ---- P3: 1024-thread block scan of packed (cnt<<32 | hit) ----
    ull v = ((ull)cnt << 32) | (unsigned)hitcnt;
    ull incl = v;
    #pragma unroll
    for (int o = 1; o < 32; o <<= 1) {
        ull x = __shfl_up_sync(0xFFFFFFFFu, incl, o);
        if (lane >= o) incl += x;
    }
    if (lane == 31) s_warp[wid] = incl;
    __syncthreads();
    if (wid == 0) {                      // exactly 32 warp totals
        ull w = s_warp[lane];
        ull iw = w;
        #pragma unroll
        for (int o = 1; o < 32; o <<= 1) {
            ull x = __shfl_up_sync(0xFFFFFFFFu, iw, o);
            if (lane >= o) iw += x;
        }
        s_warp[lane] = iw - w;           // exclusive warp offsets
        if (lane == 31) s_tot = iw;      // CTA total
    }
    __syncthreads();
    ull excl = incl - v + s_warp[wid];

    cluster.sync();    // CS2: all CTA totals published; all P2 reads done

    // cross-CTA prefix: 8 DSMEM reads, staged through shared
    if (t < NCLUS) s_peer[t] = *cluster.map_shared_rank(&s_tot, t);
    // re-zero cell counters for next replay (all P2 reads finished at CS2)
    for (int idx = gid; idx < NCELL; idx += NTH) g_cellcnt[idx] = 0;
    __syncthreads();
    ull pre = 0;
    #pragma unroll
    for (int b = 0; b < NCLUS; b++)
        if (b < crank) pre += s_peer[b];

    const ull tot  = pre + excl;
    const int offc = (int)(tot >> 32);         // my first candidate slot
    const int offh = (int)(tot & 0xFFFFFFFFu); // my first hit rank
    const int limitb = min(*d_lb, MAXB);
    const int ln     = *d_ln;

    // ---- P4: resolve hits within both cutoffs (data in registers/LMEM) ----
    // Broad cutoff: sorted rank < limitb - offc. Dropped candidates are always
    // the highest ranks, so unmasked prefix sums stay exact for emitters.
    if (gid < n && offc < limitb && hitcnt > 0) {
        const int survive = min(cnt, limitb - offc);
        for (int k = 0; k < cnt; k++) {
            int key = keys[k];
            if (!(key & 1)) continue;
            int rank = 0, hrank = 0;
            #pragma unroll 4
            for (int m = 0; m < cnt; m++) {
                int km = keys[m];
                int lt = (km < key) ? 1 : 0;   // distinct j -> strict order
                rank  += lt;
                hrank += lt & km;              // lt && hit-bit
            }
            if (rank >= survive) continue;     // broad cutoff
            if (offh + hrank >= ln) continue;  // narrow cutoff
            float dx = hdx[k], dy = hdy[k], rs = hrs[k];
            float dist = sqrtf(dx * dx + dy * dy + 1e-12f);
            float sc = 0.5f * (rs - dist) / dist;
            float ddx = sc * dx, ddy = sc * dy;
            int jv = key >> 1;
            atomicAdd(&out[2 * gid + 0], -ddx);
            atomicAdd(&out[2 * gid + 1], -ddy);
            atomicAdd(&out[2 * jv  + 0],  ddx);
            atomicAdd(&out[2 * jv  + 1],  ddy);
        }
    }

    cluster.sync();    // CS3: no CTA exits while peers may read its smem
}

// ---------------------------------------------------------------------------
extern "C" void kernel_launch(void* const* d_in, const int* in_sizes, int n_in,
                              void* d_out, int out_size) {
    const float2* centers = (const float2*)d_in[0];
    const float*  radii   = (const float*)d_in[1];
    const int*    d_lb    = (const int*)d_in[2];
    const int*    d_ln    = (const int*)d_in[3];
    const int n = in_sizes[1];
    float* out = (float*)d_out;

    collide_kernel<<<NCLUS, NTPB>>>(centers, radii, d_lb, d_ln, out, n);
}

// round 9
// speedup vs baseline: 1.3421x; 1.3421x over previous
#include <cuda_runtime.h>
#include <cuda_bf16.h>

// Three-node graph pipeline, zero spin, no in-kernel global sync:
//   K1 build   : insert bodies into cell-slot grid, copy centers to out
//   K2 query   : ring query + fused narrow phase + rank math + block scan;
//                publishes per-block totals + per-thread offsets + hit records
//   K3 resolve : global prefix from 64 block sums (L2 reads, edge-ordered),
//                cutoff checks, scatter atomics, counter cleanup
// Inter-phase ordering comes from CUDA-graph edges, not barriers/spins.
//
// N=8192, BOX=112, radii in [0.5,1.0) -> rsum < 2.0 -> grid cell 2.0 (56x56);
// all AABB-overlapping pairs lie within the +-1 cell ring.
// Reference semantics reproduced exactly: row-major ascending (i,j) candidate
// order, cutoffs limit_broad=4N (candidates) and limit_narrow=N (hits).

#define MAXN  8192
#define MAXB  (4 * MAXN)
#define GDIM  56
#define NCELL (GDIM * GDIM)
#define CAPC  20            // bodies/cell cap (avg 2.6; Poisson tail safe)
#define CAPR  32            // candidates/row cap (avg ~4; tail safe)
#define NBLK  64
#define NTPB  128
#define NTH   (NBLK * NTPB)

typedef unsigned long long ull;

__device__ int    g_cellcnt[NCELL];           // zero-init; K3 re-zeros
__device__ float4 g_cellslot[NCELL * CAPC];   // x, y, r, body-index bits
__device__ ull    g_excl[MAXN];               // per-thread packed excl offsets
__device__ ull    g_bsum[NBLK];               // per-block packed totals
__device__ float4 g_hitrec[MAXN * CAPR];      // dx, dy, rs, packed j|rank|hrank

// ---------------------------------------------------------------------------
__global__ void __launch_bounds__(NTPB)
build_kernel(const float2* __restrict__ c, const float* __restrict__ r,
             float* __restrict__ out, int n) {
    int gid = blockIdx.x * NTPB + threadIdx.x;
    if (gid >= n) return;
    float2 ci = c[gid];
    float  ri = r[gid];
    ((float2*)out)[gid] = ci;
    int cx = min(GDIM - 1, max(0, (int)(ci.x * 0.5f)));
    int cy = min(GDIM - 1, max(0, (int)(ci.y * 0.5f)));
    int cell = cy * GDIM + cx;
    int slot = atomicAdd(&g_cellcnt[cell], 1);
    if (slot < CAPC)
        g_cellslot[cell * CAPC + slot] =
            make_float4(ci.x, ci.y, ri, __int_as_float(gid));
}

// ---------------------------------------------------------------------------
__global__ void __launch_bounds__(NTPB)
query_kernel(const float2* __restrict__ c, const float* __restrict__ r, int n) {
    __shared__ ull s_ws[NTPB / 32 + 1];
    const int t    = threadIdx.x;
    const int lane = t & 31;
    const int wid  = t >> 5;
    const int bid  = blockIdx.x;
    const int gid  = bid * NTPB + t;

    // ring query -> register/LMEM candidate list + fused narrow test
    int keys[CAPR];                          // (j<<1) | hit
    float hdx[CAPR], hdy[CAPR], hrs[CAPR];
    int cnt = 0, hitcnt = 0;
    if (gid < n) {
        float2 ci = c[gid];
        float  ri = r[gid];
        int cx = min(GDIM - 1, max(0, (int)(ci.x * 0.5f)));
        int cy = min(GDIM - 1, max(0, (int)(ci.y * 0.5f)));
        int cell9[9], cc9[9];
        #pragma unroll
        for (int s = 0; s < 9; s++) {
            int yy = cy + s / 3 - 1;
            int xx = cx + s % 3 - 1;
            bool v = (yy >= 0) & (yy < GDIM) & (xx >= 0) & (xx < GDIM);
            int cell = v ? yy * GDIM + xx : 0;
            cell9[s] = cell;
            cc9[s]   = v ? g_cellcnt[cell] : 0;   // 9 independent LDGs
        }
        #pragma unroll
        for (int s = 0; s < 9; s++) {
            int cc = min(cc9[s], CAPC);
            const float4* base = &g_cellslot[cell9[s] * CAPC];
            #pragma unroll 4
            for (int q = 0; q < cc; q++) {
                float4 b = base[q];
                int j = __float_as_int(b.w);
                if (j <= gid) continue;
                float rs = ri + b.z;
                float dx = b.x - ci.x;
                float dy = b.y - ci.y;
                if (fabsf(dx) <= rs && fabsf(dy) <= rs) {
                    if (cnt < CAPR) {
                        // depth>0  <=>  d2 + eps < rs^2 (exact equivalence)
                        float d2 = dx * dx + dy * dy + 1e-12f;
                        int hit = (d2 < rs * rs) ? 1 : 0;
                        keys[cnt] = (j << 1) | hit;
                        if (hit) {
                            hdx[cnt] = dx; hdy[cnt] = dy; hrs[cnt] = rs;
                            hitcnt++;
                        }
                    }
                    cnt++;
                }
            }
        }
        if (cnt > CAPR) cnt = CAPR;
    }

    // block scan of packed (cnt<<32 | hitcnt)
    ull v = ((ull)cnt << 32) | (unsigned)hitcnt;
    ull incl = v;
    #pragma unroll
    for (int o = 1; o < 32; o <<= 1) {
        ull x = __shfl_up_sync(0xFFFFFFFFu, incl, o);
        if (lane >= o) incl += x;
    }
    if (lane == 31) s_ws[wid] = incl;
    __syncthreads();
    if (wid == 0 && lane == 0) {
        ull run = 0;
        #pragma unroll
        for (int w = 0; w < NTPB / 32; w++) {
            ull x = s_ws[w];
            s_ws[w] = run;
            run += x;
        }
        s_ws[NTPB / 32] = run;
    }
    __syncthreads();
    ull excl = incl - v + s_ws[wid];

    if (gid < n) g_excl[gid] = excl;
    if (t == 0)  g_bsum[bid] = s_ws[NTPB / 32];

    // emit compact hit records with precomputed ranks (order irrelevant)
    if (gid < n && hitcnt > 0) {
        int idx = 0;
        for (int k = 0; k < cnt; k++) {
            int key = keys[k];
            if (!(key & 1)) continue;
            int rank = 0, hrank = 0;
            #pragma unroll 4
            for (int m = 0; m < cnt; m++) {
                int km = keys[m];
                int lt = (km < key) ? 1 : 0;   // distinct j -> strict order
                rank  += lt;
                hrank += lt & km;              // lt && hit-bit of m
            }
            int jv = key >> 1;
            int packed = (jv << 10) | (rank << 5) | hrank;  // 13+5+5 bits
            g_hitrec[gid * CAPR + idx] =
                make_float4(hdx[k], hdy[k], hrs[k], __int_as_float(packed));
            idx++;
        }
    }
}

// ---------------------------------------------------------------------------
__global__ void __launch_bounds__(NTPB)
resolve_kernel(float* __restrict__ out,
               const int* __restrict__ d_lb, const int* __restrict__ d_ln,
               int n) {
    __shared__ ull s_sum[NBLK];
    const int t   = threadIdx.x;
    const int bid = blockIdx.x;
    const int gid = bid * NTPB + t;

    if (t < NBLK) s_sum[t] = g_bsum[t];
    // cleanup cell counters for next replay (K2 done reading: edge-ordered)
    for (int idx = gid; idx < NCELL; idx += NTH) g_cellcnt[idx] = 0;
    __syncthreads();

    if (gid >= n) return;
    ull pre = 0;
    #pragma unroll
    for (int b = 0; b < NBLK; b++)
        if (b < bid) pre += s_sum[b];

    ull my  = g_excl[gid];
    ull nxt = (t == NTPB - 1) ? s_sum[bid] : g_excl[gid + 1];
    const int cnt    = (int)((nxt >> 32) - (my >> 32));
    const int hitcnt = (int)((nxt & 0xFFFFFFFFu) - (my & 0xFFFFFFFFu));
    if (hitcnt == 0) return;
    const int offc = (int)((pre + my) >> 32);
    const int offh = (int)((pre + my) & 0xFFFFFFFFu);
    const int limitb = min(*d_lb, MAXB);
    const int ln     = *d_ln;
    if (offc >= limitb) return;
    // Broad cutoff: sorted rank < limitb - offc. Dropped candidates are always
    // the highest ranks, so unmasked prefix sums stay exact for emitters.
    const int survive = min(cnt, limitb - offc);

    float2 neg = make_float2(0.f, 0.f);
    for (int k = 0; k < hitcnt; k++) {
        float4 rec = g_hitrec[gid * CAPR + k];
        int packed = __float_as_int(rec.w);
        int hrank  = packed & 31;
        int rank   = (packed >> 5) & 31;
        int jv     = packed >> 10;
        if (rank >= survive) continue;        // broad cutoff
        if (offh + hrank >= ln) continue;     // narrow cutoff
        float dx = rec.x, dy = rec.y, rs = rec.z;
        float dist = sqrtf(dx * dx + dy * dy + 1e-12f);
        float sc = 0.5f * (rs - dist) / dist;
        float ddx = sc * dx, ddy = sc * dy;
        neg.x -= ddx; neg.y -= ddy;
        atomicAdd(&out[2 * jv + 0], ddx);
        atomicAdd(&out[2 * jv + 1], ddy);
    }
    if (neg.x != 0.f || neg.y != 0.f) {       // accumulate own-side once
        atomicAdd(&out[2 * gid + 0], neg.x);
        atomicAdd(&out[2 * gid + 1], neg.y);
    }
}

// ---------------------------------------------------------------------------
extern "C" void kernel_launch(void* const* d_in, const int* in_sizes, int n_in,
                              void* d_out, int out_size) {
    const float2* centers = (const float2*)d_in[0];
    const float*  radii   = (const float*)d_in[1];
    const int*    d_lb    = (const int*)d_in[2];
    const int*    d_ln    = (const int*)d_in[3];
    const int n = in_sizes[1];
    float* out = (float*)d_out;

    build_kernel<<<NBLK, NTPB>>>(centers, radii, out, n);
    query_kernel<<<NBLK, NTPB>>>(centers, radii, n);
    resolve_kernel<<<NBLK, NTPB>>>(out, d_lb, d_ln, n);
}

// round 10
// speedup vs baseline: 1.3785x; 1.0271x over previous
#include <cuda_runtime.h>
#include <cuda_bf16.h>

// Two-node graph pipeline:
//   K1 build : insert bodies into parity-selected cell grid; the LAST
//              finishing block bumps g_epoch (graph edge publishes it to K2).
//   K2 query+resolve : ring query + fused narrow phase (keys-only LMEM),
//              packed block scan, tagged single-word decoupled lookback for
//              the cross-block prefix (short spin; blocks are concurrent),
//              then immediate in-register resolve with exact cutoffs, plus
//              race-free cleanup of the other parity's cell counters.
//
// N=8192, BOX=112, radii in [0.5,1.0) -> rsum < 2.0 -> grid cell 2.0 (56x56);
// all AABB-overlapping pairs lie within the +-1 cell ring.
// Reference semantics reproduced exactly: row-major ascending (i,j) candidate
// order, cutoffs limit_broad=4N (candidates) and limit_narrow=N (hits).

#define MAXN  8192
#define MAXB  (4 * MAXN)
#define GDIM  56
#define NCELL (GDIM * GDIM)
#define CAPC  20            // bodies/cell cap (avg 2.6; Poisson tail safe)
#define CAPR  32            // candidates/row cap (avg ~4; tail safe)
#define NBLK  64
#define NTPB  128
#define NTH   (NBLK * NTPB)

typedef unsigned long long ull;

__device__ unsigned     g_done  = 0;           // K1 completion counter (self-resets)
__device__ unsigned     g_epoch = 0;           // +1 per launch, by K1's last block
__device__ int          g_cellcnt[2][NCELL];   // parity double buffer
__device__ float4       g_cellslot[2][NCELL * CAPC];
__device__ volatile ull g_flag[NBLK];          // (tag<<32)|(cnt<<16)|hit

// ---------------------------------------------------------------------------
__global__ void __launch_bounds__(NTPB)
build_kernel(const float2* __restrict__ c, const float* __restrict__ r,
             float* __restrict__ out, int n) {
    const int gid = blockIdx.x * NTPB + threadIdx.x;
    // E is stable during K1: only incremented below after ALL blocks finish
    // inserting (counter), and K2 never touches it.
    const unsigned par = *(volatile unsigned*)&g_epoch & 1u;
    if (gid < n) {
        float2 ci = c[gid];
        float  ri = r[gid];
        ((float2*)out)[gid] = ci;
        int cx = min(GDIM - 1, max(0, (int)(ci.x * 0.5f)));
        int cy = min(GDIM - 1, max(0, (int)(ci.y * 0.5f)));
        int cell = cy * GDIM + cx;
        int slot = atomicAdd(&g_cellcnt[par][cell], 1);
        if (slot < CAPC)
            g_cellslot[par][cell * CAPC + slot] =
                make_float4(ci.x, ci.y, ri, __int_as_float(gid));
    }
    __syncthreads();
    if (threadIdx.x == 0) {
        __threadfence();
        unsigned old = atomicAdd(&g_done, 1u);
        if (old == gridDim.x - 1) {       // last block to finish
            g_done = 0;
            atomicAdd(&g_epoch, 1u);      // K2 sees this via the graph edge
        }
    }
}

// ---------------------------------------------------------------------------
__global__ void __launch_bounds__(NTPB)
query_resolve_kernel(const float2* __restrict__ c, const float* __restrict__ r,
                     const int* __restrict__ d_lb, const int* __restrict__ d_ln,
                     float* __restrict__ out, int n) {
    __shared__ ull s_ws[NTPB / 32 + 1];
    __shared__ ull s_pre;
    const int t    = threadIdx.x;
    const int lane = t & 31;
    const int wid  = t >> 5;
    const int bid  = blockIdx.x;
    const int gid  = bid * NTPB + t;

    const unsigned E   = *(volatile unsigned*)&g_epoch;  // post-increment value
    const unsigned par = (E - 1u) & 1u;                  // buffer K1 filled

    // ---- query: ring cells -> keys (LMEM) + fused narrow test ----
    int keys[CAPR];                  // (j<<1) | hit
    int cnt = 0, hitcnt = 0;
    float2 ci = make_float2(0.f, 0.f);
    float  ri = 0.f;
    if (gid < n) {
        ci = c[gid];
        ri = r[gid];
        int cx = min(GDIM - 1, max(0, (int)(ci.x * 0.5f)));
        int cy = min(GDIM - 1, max(0, (int)(ci.y * 0.5f)));
        int cell9[9], cc9[9];
        #pragma unroll
        for (int s = 0; s < 9; s++) {
            int yy = cy + s / 3 - 1;
            int xx = cx + s % 3 - 1;
            bool v = (yy >= 0) & (yy < GDIM) & (xx >= 0) & (xx < GDIM);
            int cell = v ? yy * GDIM + xx : 0;
            cell9[s] = cell;
            cc9[s]   = v ? g_cellcnt[par][cell] : 0;   // 9 independent LDGs
        }
        #pragma unroll
        for (int s = 0; s < 9; s++) {
            int cc = min(cc9[s], CAPC);
            const float4* base = &g_cellslot[par][cell9[s] * CAPC];
            #pragma unroll 4
            for (int q = 0; q < cc; q++) {
                float4 b = base[q];
                int j = __float_as_int(b.w);
                if (j <= gid) continue;
                float rs = ri + b.z;
                float dx = b.x - ci.x;
                float dy = b.y - ci.y;
                if (fabsf(dx) <= rs && fabsf(dy) <= rs) {
                    if (cnt < CAPR) {
                        // depth>0  <=>  d2 + eps < rs^2 (exact equivalence)
                        float d2 = dx * dx + dy * dy + 1e-12f;
                        int hit = (d2 < rs * rs) ? 1 : 0;
                        keys[cnt] = (j << 1) | hit;
                        hitcnt += hit;
                    }
                    cnt++;
                }
            }
        }
        if (cnt > CAPR) cnt = CAPR;
    }

    // ---- packed block scan of (cnt<<32 | hitcnt) ----
    ull v = ((ull)cnt << 32) | (unsigned)hitcnt;
    ull incl = v;
    #pragma unroll
    for (int o = 1; o < 32; o <<= 1) {
        ull x = __shfl_up_sync(0xFFFFFFFFu, incl, o);
        if (lane >= o) incl += x;
    }
    if (lane == 31) s_ws[wid] = incl;
    __syncthreads();
    if (wid == 0 && lane == 0) {
        ull run = 0;
        #pragma unroll
        for (int w = 0; w < NTPB / 32; w++) {
            ull x = s_ws[w];
            s_ws[w] = run;
            run += x;
        }
        s_ws[NTPB / 32] = run;
    }
    __syncthreads();
    ull excl = incl - v + s_ws[wid];

    // ---- tagged single-word publish + parallel decoupled lookback ----
    if (t == 0) {
        ull btot = s_ws[NTPB / 32];
        unsigned bc = (unsigned)(btot >> 32);
        unsigned bh = (unsigned)(btot & 0xFFFFFFFFu);
        g_flag[bid] = ((ull)E << 32) | ((ull)bc << 16) | (ull)bh;
        s_pre = 0;
    }
    __syncthreads();
    if (t < bid) {
        ull w;
        do { w = g_flag[t]; } while ((unsigned)(w >> 32) != E);
        ull contrib = (((w >> 16) & 0xFFFFull) << 32) | (w & 0xFFFFull);
        atomicAdd(&s_pre, contrib);
    }
    // race-free cleanup: other parity untouched this launch
    for (int idx = gid; idx < NCELL; idx += NTH) g_cellcnt[1 - par][idx] = 0;
    __syncthreads();

    const ull tot  = s_pre + excl;
    const int offc = (int)(tot >> 32);
    const int offh = (int)(tot & 0xFFFFFFFFu);
    const int limitb = min(*d_lb, MAXB);
    const int ln     = *d_ln;

    // ---- resolve: exact cutoffs, reload c[j]/r[j] only for hits ----
    // Broad cutoff: sorted rank < limitb - offc. Dropped candidates are always
    // the highest ranks, so unmasked prefix sums stay exact for emitters.
    if (gid < n && hitcnt > 0 && offc < limitb) {
        const int survive = min(cnt, limitb - offc);
        float2 neg = make_float2(0.f, 0.f);
        for (int k = 0; k < cnt; k++) {
            int key = keys[k];
            if (!(key & 1)) continue;
            int rank = 0, hrank = 0;
            #pragma unroll 4
            for (int m = 0; m < cnt; m++) {
                int km = keys[m];
                int lt = (km < key) ? 1 : 0;   // distinct j -> strict order
                rank  += lt;
                hrank += lt & km;              // lt && hit-bit of m
            }
            if (rank >= survive) continue;     // broad cutoff
            if (offh + hrank >= ln) continue;  // narrow cutoff
            int jv = key >> 1;
            float2 cj = c[jv];
            float  rj = r[jv];
            float dx = cj.x - ci.x;
            float dy = cj.y - ci.y;
            float rs = ri + rj;
            float dist = sqrtf(dx * dx + dy * dy + 1e-12f);
            float sc = 0.5f * (rs - dist) / dist;
            float ddx = sc * dx, ddy = sc * dy;
            neg.x -= ddx; neg.y -= ddy;
            atomicAdd(&out[2 * jv + 0], ddx);
            atomicAdd(&out[2 * jv + 1], ddy);
        }
        if (neg.x != 0.f || neg.y != 0.f) {
            atomicAdd(&out[2 * gid + 0], neg.x);
            atomicAdd(&out[2 * gid + 1], neg.y);
        }
    }
}

// ---------------------------------------------------------------------------
extern "C" void kernel_launch(void* const* d_in, const int* in_sizes, int n_in,
                              void* d_out, int out_size) {
    const float2* centers = (const float2*)d_in[0];
    const float*  radii   = (const float*)d_in[1];
    const int*    d_lb    = (const int*)d_in[2];
    const int*    d_ln    = (const int*)d_in[3];
    const int n = in_sizes[1];
    float* out = (float*)d_out;

    build_kernel<<<NBLK, NTPB>>>(centers, radii, out, n);
    query_resolve_kernel<<<NBLK, NTPB>>>(centers, radii, d_lb, d_ln, out, n);
}

// round 12
// speedup vs baseline: 1.3830x; 1.0033x over previous
#include <cuda_runtime.h>
#include <cuda_bf16.h>

// Two-node graph pipeline (R10 structure), re-tuned to 32 blocks x 256 threads
// so each SMSP carries 2 warps (latency overlap) while per-SM LSU load stays
// well under the issue floor.
//   K1 build : insert bodies into parity-selected cell grid; last finishing
//              block bumps g_epoch (graph edge publishes it to K2).
//   K2 query+resolve : ring query + fused narrow phase (keys-only LMEM),
//              packed block scan, tagged single-word decoupled lookback,
//              in-register resolve with exact cutoffs, and race-free cleanup
//              of the other parity's cell counters.
//
// N=8192, BOX=112, radii in [0.5,1.0) -> rsum < 2.0 -> grid cell 2.0 (56x56);
// all AABB-overlapping pairs lie within the +-1 cell ring.
// Reference semantics reproduced exactly: row-major ascending (i,j) candidate
// order, cutoffs limit_broad=4N (candidates) and limit_narrow=N (hits).

#define MAXN  8192
#define MAXB  (4 * MAXN)
#define GDIM  56
#define NCELL (GDIM * GDIM)
#define CAPC  20            // bodies/cell cap (avg 2.6; Poisson tail safe)
#define CAPR  32            // candidates/row cap (avg ~4; tail safe)
#define NBLK  32
#define NTPB  256
#define NTH   (NBLK * NTPB)

typedef unsigned long long ull;

__device__ unsigned     g_done  = 0;           // K1 completion counter (self-resets)
__device__ unsigned     g_epoch = 0;           // +1 per launch, by K1's last block
__device__ int          g_cellcnt[2][NCELL];   // parity double buffer
__device__ float4       g_cellslot[2][NCELL * CAPC];
__device__ volatile ull g_flag[NBLK];          // (tag<<32)|(cnt<<16)|hit

// ---------------------------------------------------------------------------
__global__ void __launch_bounds__(NTPB)
build_kernel(const float2* __restrict__ c, const float* __restrict__ r,
             float* __restrict__ out, int n) {
    const int gid = blockIdx.x * NTPB + threadIdx.x;
    // Epoch is stable during K1: only bumped after ALL blocks finished inserts.
    const unsigned par = *(volatile unsigned*)&g_epoch & 1u;
    if (gid < n) {
        float2 ci = c[gid];
        float  ri = r[gid];
        ((float2*)out)[gid] = ci;
        int cx = min(GDIM - 1, max(0, (int)(ci.x * 0.5f)));
        int cy = min(GDIM - 1, max(0, (int)(ci.y * 0.5f)));
        int cell = cy * GDIM + cx;
        int slot = atomicAdd(&g_cellcnt[par][cell], 1);
        if (slot < CAPC)
            g_cellslot[par][cell * CAPC + slot] =
                make_float4(ci.x, ci.y, ri, __int_as_float(gid));
    }
    __syncthreads();
    if (threadIdx.x == 0) {
        __threadfence();
        unsigned old = atomicAdd(&g_done, 1u);
        if (old == gridDim.x - 1) {       // last block to finish
            g_done = 0;
            atomicAdd(&g_epoch, 1u);      // K2 sees this via the graph edge
        }
    }
}

// ---------------------------------------------------------------------------
__global__ void __launch_bounds__(NTPB)
query_resolve_kernel(const float2* __restrict__ c, const float* __restrict__ r,
                     const int* __restrict__ d_lb, const int* __restrict__ d_ln,
                     float* __restrict__ out, int n) {
    __shared__ ull s_ws[NTPB / 32 + 1];
    __shared__ ull s_pre;
    const int t    = threadIdx.x;
    const int lane = t & 31;
    const int wid  = t >> 5;
    const int bid  = blockIdx.x;
    const int gid  = bid * NTPB + t;

    const unsigned E   = *(volatile unsigned*)&g_epoch;  // post-increment value
    const unsigned par = (E - 1u) & 1u;                  // buffer K1 filled

    // ---- query: ring cells -> keys (LMEM) + fused narrow test ----
    int keys[CAPR];                  // (j<<1) | hit
    int cnt = 0, hitcnt = 0;
    float2 ci = make_float2(0.f, 0.f);
    float  ri = 0.f;
    if (gid < n) {
        ci = c[gid];
        ri = r[gid];
        int cx = min(GDIM - 1, max(0, (int)(ci.x * 0.5f)));
        int cy = min(GDIM - 1, max(0, (int)(ci.y * 0.5f)));
        int cell9[9], cc9[9];
        #pragma unroll
        for (int s = 0; s < 9; s++) {
            int yy = cy + s / 3 - 1;
            int xx = cx + s % 3 - 1;
            bool v = (yy >= 0) & (yy < GDIM) & (xx >= 0) & (xx < GDIM);
            int cell = v ? yy * GDIM + xx : 0;
            cell9[s] = cell;
            cc9[s]   = v ? g_cellcnt[par][cell] : 0;   // 9 independent LDGs
        }
        #pragma unroll
        for (int s = 0; s < 9; s++) {
            int cc = min(cc9[s], CAPC);
            const float4* base = &g_cellslot[par][cell9[s] * CAPC];
            #pragma unroll 4
            for (int q = 0; q < cc; q++) {
                float4 b = base[q];
                int j = __float_as_int(b.w);
                if (j <= gid) continue;
                float rs = ri + b.z;
                float dx = b.x - ci.x;
                float dy = b.y - ci.y;
                if (fabsf(dx) <= rs && fabsf(dy) <= rs) {
                    if (cnt < CAPR) {
                        // depth>0  <=>  d2 + eps < rs^2 (exact equivalence)
                        float d2 = dx * dx + dy * dy + 1e-12f;
                        int hit = (d2 < rs * rs) ? 1 : 0;
                        keys[cnt] = (j << 1) | hit;
                        hitcnt += hit;
                    }
                    cnt++;
                }
            }
        }
        if (cnt > CAPR) cnt = CAPR;
    }

    // ---- packed block scan of (cnt<<32 | hitcnt) ----
    ull v = ((ull)cnt << 32) | (unsigned)hitcnt;
    ull incl = v;
    #pragma unroll
    for (int o = 1; o < 32; o <<= 1) {
        ull x = __shfl_up_sync(0xFFFFFFFFu, incl, o);
        if (lane >= o) incl += x;
    }
    if (lane == 31) s_ws[wid] = incl;
    __syncthreads();
    if (wid == 0 && lane == 0) {
        ull run = 0;
        #pragma unroll
        for (int w = 0; w < NTPB / 32; w++) {
            ull x = s_ws[w];
            s_ws[w] = run;
            run += x;
        }
        s_ws[NTPB / 32] = run;
    }
    __syncthreads();
    ull excl = incl - v + s_ws[wid];

    // ---- tagged single-word publish + parallel decoupled lookback ----
    if (t == 0) {
        ull btot = s_ws[NTPB / 32];
        unsigned bc = (unsigned)(btot >> 32);
        unsigned bh = (unsigned)(btot & 0xFFFFFFFFu);
        g_flag[bid] = ((ull)E << 32) | ((ull)bc << 16) | (ull)bh;
        s_pre = 0;
    }
    __syncthreads();
    if (t < bid) {
        ull w;
        do { w = g_flag[t]; } while ((unsigned)(w >> 32) != E);
        ull contrib = (((w >> 16) & 0xFFFFull) << 32) | (w & 0xFFFFull);
        atomicAdd(&s_pre, contrib);
    }
    // race-free cleanup: other parity untouched this launch
    for (int idx = gid; idx < NCELL; idx += NTH) g_cellcnt[1 - par][idx] = 0;
    __syncthreads();

    const ull tot  = s_pre + excl;
    const int offc = (int)(tot >> 32);
    const int offh = (int)(tot & 0xFFFFFFFFu);
    const int limitb = min(*d_lb, MAXB);
    const int ln     = *d_ln;

    // ---- resolve: exact cutoffs, reload c[j]/r[j] only for hits ----
    // Broad cutoff: sorted rank < limitb - offc. Dropped candidates are always
    // the highest ranks, so unmasked prefix sums stay exact for emitters.
    if (gid < n && hitcnt > 0 && offc < limitb) {
        const int survive = min(cnt, limitb - offc);
        float2 neg = make_float2(0.f, 0.f);
        for (int k = 0; k < cnt; k++) {
            int key = keys[k];
            if (!(key & 1)) continue;
            int rank = 0, hrank = 0;
            #pragma unroll 4
            for (int m = 0; m < cnt; m++) {
                int km = keys[m];
                int lt = (km < key) ? 1 : 0;   // distinct j -> strict order
                rank  += lt;
                hrank += lt & km;              // lt && hit-bit of m
            }
            if (rank >= survive) continue;     // broad cutoff
            if (offh + hrank >= ln) continue;  // narrow cutoff
            int jv = key >> 1;
            float2 cj = c[jv];
            float  rj = r[jv];
            float dx = cj.x - ci.x;
            float dy = cj.y - ci.y;
            float rs = ri + rj;
            float dist = sqrtf(dx * dx + dy * dy + 1e-12f);
            float sc = 0.5f * (rs - dist) / dist;
            float ddx = sc * dx, ddy = sc * dy;
            neg.x -= ddx; neg.y -= ddy;
            atomicAdd(&out[2 * jv + 0], ddx);
            atomicAdd(&out[2 * jv + 1], ddy);
        }
        if (neg.x != 0.f || neg.y != 0.f) {
            atomicAdd(&out[2 * gid + 0], neg.x);
            atomicAdd(&out[2 * gid + 1], neg.y);
        }
    }
}

// ---------------------------------------------------------------------------
extern "C" void kernel_launch(void* const* d_in, const int* in_sizes, int n_in,
                              void* d_out, int out_size) {
    const float2* centers = (const float2*)d_in[0];
    const float*  radii   = (const float*)d_in[1];
    const int*    d_lb    = (const int*)d_in[2];
    const int*    d_ln    = (const int*)d_in[3];
    const int n = in_sizes[1];
    float* out = (float*)d_out;

    build_kernel<<<NBLK, NTPB>>>(centers, radii, out, n);
    query_resolve_kernel<<<NBLK, NTPB>>>(centers, radii, d_lb, d_ln, out, n);
}

// round 14
// speedup vs baseline: 1.7080x; 1.2350x over previous
#include <cuda_runtime.h>
#include <cuda_bf16.h>

// Two-node graph pipeline (R12 structure) with a shortened per-warp critical
// path: 4-way MLP slot loads in the query, hit-bit-driven resolve, and per-hit
// geometry cached at query time (no L2 reloads in resolve).
//   K1 build : insert bodies into parity-selected cell grid; last finishing
//              block bumps g_epoch (graph edge publishes it to K2).
//   K2 query+resolve : ring query + fused narrow phase, packed block scan,
//              tagged single-word decoupled lookback, in-register resolve
//              with exact cutoffs, race-free cleanup of other parity.
//
// N=8192, BOX=112, radii in [0.5,1.0) -> rsum < 2.0 -> grid cell 2.0 (56x56);
// all AABB-overlapping pairs lie within the +-1 cell ring.
// Reference semantics reproduced exactly: row-major ascending (i,j) candidate
// order, cutoffs limit_broad=4N (candidates) and limit_narrow=N (hits).

#define MAXN  8192
#define MAXB  (4 * MAXN)
#define GDIM  56
#define NCELL (GDIM * GDIM)
#define CAPC  20            // bodies/cell cap (avg 2.6; Poisson tail safe)
#define CAPR  32            // candidates/row cap (avg ~8; tail safe)
#define NBLK  32
#define NTPB  256
#define NTH   (NBLK * NTPB)

typedef unsigned long long ull;

__device__ unsigned     g_done  = 0;           // K1 completion counter (self-resets)
__device__ unsigned     g_epoch = 0;           // +1 per launch, by K1's last block
__device__ int          g_cellcnt[2][NCELL];   // parity double buffer
__device__ float4       g_cellslot[2][NCELL * CAPC];
__device__ volatile ull g_flag[NBLK];          // (tag<<32)|(cnt<<16)|hit

// ---------------------------------------------------------------------------
__global__ void __launch_bounds__(NTPB)
build_kernel(const float2* __restrict__ c, const float* __restrict__ r,
             float* __restrict__ out, int n) {
    const int gid = blockIdx.x * NTPB + threadIdx.x;
    // Epoch is stable during K1: only bumped after ALL blocks finished inserts.
    const unsigned par = *(volatile unsigned*)&g_epoch & 1u;
    if (gid < n) {
        float2 ci = c[gid];
        float  ri = r[gid];
        ((float2*)out)[gid] = ci;
        int cx = min(GDIM - 1, max(0, (int)(ci.x * 0.5f)));
        int cy = min(GDIM - 1, max(0, (int)(ci.y * 0.5f)));
        int cell = cy * GDIM + cx;
        int slot = atomicAdd(&g_cellcnt[par][cell], 1);
        if (slot < CAPC)
            g_cellslot[par][cell * CAPC + slot] =
                make_float4(ci.x, ci.y, ri, __int_as_float(gid));
    }
    __syncthreads();
    if (threadIdx.x == 0) {
        __threadfence();
        unsigned old = atomicAdd(&g_done, 1u);
        if (old == gridDim.x - 1) {       // last block to finish
            g_done = 0;
            atomicAdd(&g_epoch, 1u);      // K2 sees this via the graph edge
        }
    }
}

// ---------------------------------------------------------------------------
__global__ void __launch_bounds__(NTPB)
query_resolve_kernel(const float2* __restrict__ c, const float* __restrict__ r,
                     const int* __restrict__ d_lb, const int* __restrict__ d_ln,
                     float* __restrict__ out, int n) {
    __shared__ ull s_ws[NTPB / 32 + 1];
    __shared__ ull s_pre;
    const int t    = threadIdx.x;
    const int lane = t & 31;
    const int wid  = t >> 5;
    const int bid  = blockIdx.x;
    const int gid  = bid * NTPB + t;

    const unsigned E   = *(volatile unsigned*)&g_epoch;  // post-increment value
    const unsigned par = (E - 1u) & 1u;                  // buffer K1 filled

    // ---- query: ring cells -> keys + cached hit geometry ----
    int keys[CAPR];                  // (j<<1) | hit
    float hdx[CAPR], hdy[CAPR], hrs[CAPR];
    unsigned hitmask = 0;
    int cnt = 0;
    float2 ci = make_float2(0.f, 0.f);
    float  ri = 0.f;

#define PROC(b) do {                                                         \
        int   _j  = __float_as_int((b).w);                                   \
        float _rs = ri + (b).z;                                              \
        float _dx = (b).x - ci.x;                                            \
        float _dy = (b).y - ci.y;                                            \
        bool  _acc = (_j > gid) & (fabsf(_dx) <= _rs) & (fabsf(_dy) <= _rs); \
        if (_acc) {                                                          \
            if (cnt < CAPR) {                                                \
                float _d2 = _dx * _dx + _dy * _dy + 1e-12f;                  \
                int _hit = (_d2 < _rs * _rs) ? 1 : 0;                        \
                keys[cnt] = (_j << 1) | _hit;                                \
                hitmask |= (unsigned)_hit << cnt;                            \
                hdx[cnt] = _dx; hdy[cnt] = _dy; hrs[cnt] = _rs;              \
            }                                                                \
            cnt++;                                                           \
        }                                                                    \
    } while (0)

    if (gid < n) {
        ci = c[gid];
        ri = r[gid];
        int cx = min(GDIM - 1, max(0, (int)(ci.x * 0.5f)));
        int cy = min(GDIM - 1, max(0, (int)(ci.y * 0.5f)));
        int cell9[9], cc9[9];
        #pragma unroll
        for (int s = 0; s < 9; s++) {
            int yy = cy + s / 3 - 1;
            int xx = cx + s % 3 - 1;
            bool v = (yy >= 0) & (yy < GDIM) & (xx >= 0) & (xx < GDIM);
            int cell = v ? yy * GDIM + xx : 0;
            cell9[s] = cell;
            cc9[s]   = v ? g_cellcnt[par][cell] : 0;   // 9 independent LDGs
        }
        #pragma unroll
        for (int s = 0; s < 9; s++) {
            int cc = min(cc9[s], CAPC);
            const float4* base = &g_cellslot[par][cell9[s] * CAPC];
            int q = 0;
            for (; q + 3 < cc; q += 4) {         // 4 independent LDG.128s
                float4 b0 = base[q];
                float4 b1 = base[q + 1];
                float4 b2 = base[q + 2];
                float4 b3 = base[q + 3];
                PROC(b0); PROC(b1); PROC(b2); PROC(b3);
            }
            for (; q < cc; q++) {
                float4 b = base[q];
                PROC(b);
            }
        }
        if (cnt > CAPR) cnt = CAPR;
    }
#undef PROC
    const int hitcnt = __popc(hitmask);

    // ---- packed block scan of (cnt<<32 | hitcnt) ----
    ull v = ((ull)cnt << 32) | (unsigned)hitcnt;
    ull incl = v;
    #pragma unroll
    for (int o = 1; o < 32; o <<= 1) {
        ull x = __shfl_up_sync(0xFFFFFFFFu, incl, o);
        if (lane >= o) incl += x;
    }
    if (lane == 31) s_ws[wid] = incl;
    __syncthreads();
    if (wid == 0 && lane == 0) {
        ull run = 0;
        #pragma unroll
        for (int w = 0; w < NTPB / 32; w++) {
            ull x = s_ws[w];
            s_ws[w] = run;
            run += x;
        }
        s_ws[NTPB / 32] = run;
    }
    __syncthreads();
    ull excl = incl - v + s_ws[wid];

    // ---- tagged single-word publish + parallel decoupled lookback ----
    if (t == 0) {
        ull btot = s_ws[NTPB / 32];
        unsigned bc = (unsigned)(btot >> 32);
        unsigned bh = (unsigned)(btot & 0xFFFFFFFFu);
        g_flag[bid] = ((ull)E << 32) | ((ull)bc << 16) | (ull)bh;
        s_pre = 0;
    }
    __syncthreads();
    if (t < bid) {
        ull w;
        do { w = g_flag[t]; } while ((unsigned)(w >> 32) != E);
        ull contrib = (((w >> 16) & 0xFFFFull) << 32) | (w & 0xFFFFull);
        atomicAdd(&s_pre, contrib);
    }
    // race-free cleanup: other parity untouched this launch
    for (int idx = gid; idx < NCELL; idx += NTH) g_cellcnt[1 - par][idx] = 0;
    __syncthreads();

    const ull tot  = s_pre + excl;
    const int offc = (int)(tot >> 32);
    const int offh = (int)(tot & 0xFFFFFFFFu);
    const int limitb = min(*d_lb, MAXB);
    const int ln     = *d_ln;

    // ---- resolve: hit-bit walk, exact cutoffs, zero reloads ----
    // Broad cutoff: sorted rank < limitb - offc. Dropped candidates are always
    // the highest ranks, so unmasked prefix sums stay exact for emitters.
    if (gid < n && hitmask && offc < limitb) {
        const int survive = min(cnt, limitb - offc);
        float2 neg = make_float2(0.f, 0.f);
        unsigned m = hitmask;
        while (m) {
            int k = __ffs(m) - 1;
            m &= m - 1;
            int key = keys[k];
            int rank = 0, hrank = 0;
            #pragma unroll 4
            for (int q = 0; q < cnt; q++) {       // branch-free rank loop
                int kq = keys[q];
                int lt = (kq < key) ? 1 : 0;      // distinct j -> strict order
                rank  += lt;
                hrank += lt & kq;                 // lt && hit-bit of q
            }
            if (rank >= survive) continue;        // broad cutoff
            if (offh + hrank >= ln) continue;     // narrow cutoff
            float dx = hdx[k], dy = hdy[k], rs = hrs[k];
            float dist = sqrtf(dx * dx + dy * dy + 1e-12f);
            float sc = 0.5f * (rs - dist) / dist;
            float ddx = sc * dx, ddy = sc * dy;
            int jv = key >> 1;
            neg.x -= ddx; neg.y -= ddy;
            atomicAdd(&out[2 * jv + 0], ddx);
            atomicAdd(&out[2 * jv + 1], ddy);
        }
        if (neg.x != 0.f || neg.y != 0.f) {
            atomicAdd(&out[2 * gid + 0], neg.x);
            atomicAdd(&out[2 * gid + 1], neg.y);
        }
    }
}

// ---------------------------------------------------------------------------
extern "C" void kernel_launch(void* const* d_in, const int* in_sizes, int n_in,
                              void* d_out, int out_size) {
    const float2* centers = (const float2*)d_in[0];
    const float*  radii   = (const float*)d_in[1];
    const int*    d_lb    = (const int*)d_in[2];
    const int*    d_ln    = (const int*)d_in[3];
    const int n = in_sizes[1];
    float* out = (float*)d_out;

    build_kernel<<<NBLK, NTPB>>>(centers, radii, out, n);
    query_resolve_kernel<<<NBLK, NTPB>>>(centers, radii, d_lb, d_ln, out, n);
}